// round 1
// baseline (speedup 1.0000x reference)
#include <cuda_runtime.h>
#include <math.h>

#define T_SAMPLES 128
#define HID 16

__global__ void __launch_bounds__(128)
nerf_render_kernel(const float* __restrict__ o,
                   const float* __restrict__ d,
                   const float* __restrict__ tnear,
                   const float* __restrict__ tfar,
                   const float* __restrict__ noise,
                   const float* __restrict__ W1,      // (3,16)
                   const float* __restrict__ b1,      // (16)
                   const float* __restrict__ w_sigma, // (16,1)
                   const float* __restrict__ W_rgb,   // (16,3)
                   float* __restrict__ out,           // (N,5)
                   int N)
{
    const int ray = blockIdx.x * blockDim.x + threadIdx.x;
    if (ray >= N) return;

    // ---- load weights into registers (broadcast, loop-invariant) ----
    float w1x[HID], w1y[HID], w1z[HID], bb[HID], ws[HID];
    float wr0[HID], wr1[HID], wr2[HID];
#pragma unroll
    for (int j = 0; j < HID; j++) {
        w1x[j] = __ldg(&W1[0 * HID + j]);
        w1y[j] = __ldg(&W1[1 * HID + j]);
        w1z[j] = __ldg(&W1[2 * HID + j]);
        bb[j]  = __ldg(&b1[j]);
        ws[j]  = __ldg(&w_sigma[j]);
        wr0[j] = __ldg(&W_rgb[j * 3 + 0]);
        wr1[j] = __ldg(&W_rgb[j * 3 + 1]);
        wr2[j] = __ldg(&W_rgb[j * 3 + 2]);
    }

    // ---- per-ray state ----
    const float ox = o[3 * ray + 0], oy = o[3 * ray + 1], oz = o[3 * ray + 2];
    const float dx = d[3 * ray + 0], dy = d[3 * ray + 1], dz = d[3 * ray + 2];
    const float dn = sqrtf(dx * dx + dy * dy + dz * dz);
    const float tn = tnear[ray];
    const float tf = tfar[ray];
    const float range = tf - tn;
    const float invT = 1.0f / (float)T_SAMPLES;

    // t = 0 sample position
    float ts_prev = fmaf(range, noise[ray] * invT, tn);

    float Ttr = 1.0f;            // running transmittance (product of exp(-sd))
    float c0 = 0.f, c1 = 0.f, c2 = 0.f, dep = 0.f, alp = 0.f;

#pragma unroll 2
    for (int t = 1; t <= T_SAMPLES; t++) {
        float ts;
        if (t < T_SAMPLES) {
            float u = noise[(size_t)t * N + ray];
            ts = fmaf(range, ((float)t + u) * invT, tn);
        } else {
            ts = tf;
        }
        const float delta = ts - ts_prev;

        // ---- evaluate MLP at ts_prev ----
        const float x = fmaf(ts_prev, dx, ox);
        const float y = fmaf(ts_prev, dy, oy);
        const float z = fmaf(ts_prev, dz, oz);

        float acc_s = 0.f, r0 = 0.f, r1 = 0.f, r2 = 0.f;
#pragma unroll
        for (int j = 0; j < HID; j++) {
            float h = fmaf(x, w1x[j], fmaf(y, w1y[j], fmaf(z, w1z[j], bb[j])));
            h = fmaxf(h, 0.0f);
            acc_s = fmaf(h, ws[j], acc_s);
            r0 = fmaf(h, wr0[j], r0);
            r1 = fmaf(h, wr1[j], r1);
            r2 = fmaf(h, wr2[j], r2);
        }

        // softplus (stable): max(x,0) + log(1 + exp(-|x|))
        const float sigma = fmaxf(acc_s, 0.0f)
                          + __logf(1.0f + __expf(-fabsf(acc_s)));
        const float sd = sigma * delta * dn;
        const float e  = __expf(-sd);
        const float w  = Ttr * (1.0f - e);
        Ttr *= e;

        // sigmoids
        const float s0 = __fdividef(1.0f, 1.0f + __expf(-r0));
        const float s1 = __fdividef(1.0f, 1.0f + __expf(-r1));
        const float s2 = __fdividef(1.0f, 1.0f + __expf(-r2));

        c0  = fmaf(w, s0, c0);
        c1  = fmaf(w, s1, c1);
        c2  = fmaf(w, s2, c2);
        dep = fmaf(w, ts_prev, dep);
        alp += w;

        ts_prev = ts;
    }

    out[5 * ray + 0] = c0;
    out[5 * ray + 1] = c1;
    out[5 * ray + 2] = c2;
    out[5 * ray + 3] = dep;
    out[5 * ray + 4] = alp;
}

extern "C" void kernel_launch(void* const* d_in, const int* in_sizes, int n_in,
                              void* d_out, int out_size)
{
    const float* o       = (const float*)d_in[0];
    const float* d       = (const float*)d_in[1];
    const float* tnear   = (const float*)d_in[2];
    const float* tfar    = (const float*)d_in[3];
    const float* noise   = (const float*)d_in[4];
    const float* W1      = (const float*)d_in[5];
    const float* b1      = (const float*)d_in[6];
    const float* w_sigma = (const float*)d_in[7];
    const float* W_rgb   = (const float*)d_in[8];
    float* out = (float*)d_out;

    const int N = in_sizes[2];  // tnear has N elements
    const int threads = 128;
    const int blocks = (N + threads - 1) / threads;
    nerf_render_kernel<<<blocks, threads>>>(o, d, tnear, tfar, noise,
                                            W1, b1, w_sigma, W_rgb, out, N);
}